// round 15
// baseline (speedup 1.0000x reference)
#include <cuda_runtime.h>
#include <cuda_bf16.h>
#include <math.h>

#define PCAP 40
#define NEG_INF (-3.4e38f)

__device__ __constant__ float c_cos8[8] = {
    1.0f, 0.5403023058681398f, -0.4161468365471424f, -0.9899924966004454f,
    -0.6536436208636119f, 0.2836621854632263f, 0.9601702866503661f, 0.7539022543433046f
};
__device__ __constant__ float c_sin8[8] = {
    0.0f, 0.8414709848078965f, 0.9092974268256817f, 0.1411200080598672f,
    -0.7568024953079282f, -0.9589242746631385f, -0.27941549819892586f, 0.6569865987187891f
};

// 128 blocks x 512 threads. block -> (b = blk>>3, chunk = blk&7; 128 tokens).
// Phase 1: warp w -> head w&3, delta segment (w>>2)*256 + lane*8, 8/lane.
//          Also emits per-row prefix max s_M[h][t-t0] as a byproduct.
// Phase 2: thread = (token, head) quad; ONE pool walk; shfl-reduce heads.
__global__ void __launch_bounds__(512)
k_all(const int* __restrict__ tok,
      const float* __restrict__ embed,
      const float* __restrict__ inw,
      const float* __restrict__ postw,
      const float* __restrict__ finw,
      const float* __restrict__ qnw,
      const float* __restrict__ knw,
      const float* __restrict__ kp,
      const float* __restrict__ vp,
      const float* __restrict__ qp,
      const float* __restrict__ op,
      const float* __restrict__ gp,
      const float* __restrict__ upw,
      const float* __restrict__ dp,
      float* __restrict__ out) {
    int tid = threadIdx.x;
    int lane = tid & 31, wid = tid >> 5;
    int b = blockIdx.x >> 3;
    int chunk = blockIdx.x & 7;
    int t0 = chunk << 7;
    int tmax = t0 + 127;

    __shared__ int    s_tok[1024];
    __shared__ float  s_emb[30];
    __shared__ float4 s_w[4][10];
    __shared__ float2 s_pool[4][PCAP];
    __shared__ int    s_pn[4];
    __shared__ float  s_part[4][4];  // inclusive max of each 256-delta segment
    __shared__ float  s_half[4][4];  // inclusive max of first 128 of each segment
    __shared__ float  s_M[4][128];   // per-row inclusive prefix max

    // ---------- phase 0: staging (independent loads) ----------
    if (tid < 4) s_pn[tid] = 0;
    if (tid < 256) {
        const int4* rowv = (const int4*)(tok + b * 1024);
        ((int4*)s_tok)[tid] = rowv[tid];
    }
    if (tid < 30) s_emb[tid] = embed[tid];
    if (tid >= 256 && tid < 296) {
        int q = tid - 256;
        int hh = q / 10, dd = q % 10;
        float e0 = embed[3 * dd], e1 = embed[3 * dd + 1], e2 = embed[3 * dd + 2];
        float vv = (e0 * e0 + e1 * e1 + e2 * e2) * (1.0f / 3.0f);
        float rr = rsqrtf(vv + 1e-6f);
        float y0 = e0 * rr * inw[0], y1 = e1 * rr * inw[1], y2 = e2 * rr * inw[2];
        float v0 = vp[0] * y0 + vp[1] * y1 + vp[2] * y2;
        float v1 = vp[3] * y0 + vp[4] * y1 + vp[5] * y2;
        float w0 = v0 * op[0 * 8 + 2 * hh] + v1 * op[0 * 8 + 2 * hh + 1];
        float w1 = v0 * op[1 * 8 + 2 * hh] + v1 * op[1 * 8 + 2 * hh + 1];
        float w2 = v0 * op[2 * 8 + 2 * hh] + v1 * op[2 * 8 + 2 * hh + 1];
        s_w[hh][dd] = make_float4(w0, w1, w2, 0.0f);
    }

    // ---------- phase 1: score scan, 4 warps per head ----------
    int h1 = wid & 3;
    int part = wid >> 2;
    int base = part * 256 + lane * 8;

    float f8[8];
    {
        float e0 = embed[0], e1 = embed[1], e2 = embed[2];
        float vv = (e0 * e0 + e1 * e1 + e2 * e2) * (1.0f / 3.0f);
        float rr = rsqrtf(vv + 1e-6f);
        float xl0 = e0 * rr * inw[0], xl1 = e1 * rr * inw[1], xl2 = e2 * rr * inw[2];
        float k0 = kp[0] * xl0 + kp[1] * xl1 + kp[2] * xl2;
        float k1 = kp[3] * xl0 + kp[4] * xl1 + kp[5] * xl2;
        float rk = rsqrtf((k0 * k0 + k1 * k1) * 0.5f + 1e-6f);
        float kn0 = k0 * rk * knw[0], kn1 = k1 * rk * knw[1];
        const float* q0r = qp + (2 * h1) * 3;
        const float* q1r = qp + (2 * h1 + 1) * 3;
        float q0 = q0r[0] * xl0 + q0r[1] * xl1 + q0r[2] * xl2;
        float q1 = q1r[0] * xl0 + q1r[1] * xl1 + q1r[2] * xl2;
        float rq = rsqrtf((q0 * q0 + q1 * q1) * 0.5f + 1e-6f);
        float qn0 = q0 * rq * qnw[0], qn1 = q1 * rq * qnw[1];
        float P = (qn0 * kn0 + qn1 * kn1) * 0.70710678118654752f;
        float X = (qn0 * kn1 - qn1 * kn0) * 0.70710678118654752f;
        float cb, sb;
        sincosf((float)base, &sb, &cb);
        float A = P * cb + X * sb;
        float B = X * cb - P * sb;
        #pragma unroll
        for (int i = 0; i < 8; i++)
            f8[i] = A * c_cos8[i] + B * c_sin8[i];
    }
    float lm = f8[0];
    #pragma unroll
    for (int i = 1; i < 8; i++) lm = fmaxf(lm, f8[i]);
    float sc = lm;
    #pragma unroll
    for (int off = 1; off < 32; off <<= 1) {
        float v = __shfl_up_sync(0xffffffffu, sc, off);
        if (lane >= off) sc = fmaxf(sc, v);
    }
    if (lane == 15) s_half[h1][part] = sc;
    if (lane == 31) s_part[h1][part] = sc;
    __syncthreads();

    {
        float wpre = NEG_INF;
        #pragma unroll
        for (int p = 0; p < 3; p++)
            if (p < part) wpre = fmaxf(wpre, s_part[h1][p]);
        float ex = __shfl_up_sync(0xffffffffu, sc, 1);
        float run = fmaxf((lane == 0) ? NEG_INF : ex, wpre);

        // fold M_low (exclusive prefix max at t0) into run: exact for
        // delta >= t0 (subset of true prefix), only tightens push for earlier
        int hc = chunk >> 1;
        float M_low = NEG_INF;
        #pragma unroll
        for (int p = 0; p < 3; p++)
            if (p < hc) M_low = fmaxf(M_low, s_part[h1][p]);
        if (chunk & 1) M_low = fmaxf(M_low, s_half[h1][hc]);
        run = fmaxf(run, M_low);

        if (base <= tmax) {
            #pragma unroll
            for (int i = 0; i < 8; i++) {
                float f = f8[i];
                int delta = base + i;
                if (f >= run - 13.0f && delta <= tmax) {
                    int idx = atomicAdd(&s_pn[h1], 1);
                    if (idx < PCAP)
                        s_pool[h1][idx] = make_float2(__int_as_float(delta), f);
                }
                run = fmaxf(run, f);
                if (delta >= t0 && delta <= tmax)
                    s_M[h1][delta - t0] = run;   // inclusive prefix max
            }
        }
    }
    __syncthreads();

    // ---------- phase 2: thread = (token, head); single pool walk ----------
    int t = t0 + (tid >> 2);
    int h = tid & 3;
    int d = s_tok[t];
    float x0 = s_emb[3 * d], x1 = s_emb[3 * d + 1], x2 = s_emb[3 * d + 2];

    float cx0, cx1, cx2;
    {
        int n = min(s_pn[h], PCAP);
        float M = s_M[h][t - t0];
        float thr = M - 13.0f;
        float sum = 0.0f, c0 = 0.0f, c1 = 0.0f, c2 = 0.0f;
        #pragma unroll 2
        for (int j = 0; j < n; j++) {
            float2 e = s_pool[h][j];
            int dj = __float_as_int(e.x);
            if (dj <= t && e.y > thr) {
                float p = __expf(e.y - M);
                sum += p;
                float4 w = s_w[h][s_tok[t - dj]];
                c0 += p * w.x;
                c1 += p * w.y;
                c2 += p * w.z;
            }
        }
        float inv = 1.0f / sum;
        cx0 = c0 * inv;
        cx1 = c1 * inv;
        cx2 = c2 * inv;
    }
    #pragma unroll
    for (int off = 1; off < 4; off <<= 1) {
        cx0 += __shfl_xor_sync(0xffffffffu, cx0, off);
        cx1 += __shfl_xor_sync(0xffffffffu, cx1, off);
        cx2 += __shfl_xor_sync(0xffffffffu, cx2, off);
    }
    x0 += cx0;
    x1 += cx1;
    x2 += cx2;

    // ---------- epilogue: post-norm; MLP split across quad; final + logits ---
    float var = (x0 * x0 + x1 * x1 + x2 * x2) * (1.0f / 3.0f);
    float r = rsqrtf(var + 1e-6f);
    float y0 = x0 * r * postw[0];
    float y1 = x1 * r * postw[1];
    float y2 = x2 * r * postw[2];
    float d0, d1, d2;
    {
        int j = h;
        float g = gp[j * 3] * y0 + gp[j * 3 + 1] * y1 + gp[j * 3 + 2] * y2;
        float u = upw[j * 3] * y0 + upw[j * 3 + 1] * y1 + upw[j * 3 + 2] * y2;
        float sil = g / (1.0f + __expf(-g));
        float hh = sil * u;
        d0 = dp[0 * 4 + j] * hh;
        d1 = dp[1 * 4 + j] * hh;
        d2 = dp[2 * 4 + j] * hh;
    }
    #pragma unroll
    for (int off = 1; off < 4; off <<= 1) {
        d0 += __shfl_xor_sync(0xffffffffu, d0, off);
        d1 += __shfl_xor_sync(0xffffffffu, d1, off);
        d2 += __shfl_xor_sync(0xffffffffu, d2, off);
    }
    x0 += d0;
    x1 += d1;
    x2 += d2;

    float var2 = (x0 * x0 + x1 * x1 + x2 * x2) * (1.0f / 3.0f);
    float r2 = rsqrtf(var2 + 1e-6f);
    float z0 = x0 * r2 * finw[0];
    float z1 = x1 * r2 * finw[1];
    float z2 = x2 * r2 * finw[2];

    float* o = out + (size_t)(b * 1024 + t) * 10;
    {
        int da = 2 * h, db = 2 * h + 1;
        float la = z0 * s_emb[3 * da] + z1 * s_emb[3 * da + 1] + z2 * s_emb[3 * da + 2];
        float lb = z0 * s_emb[3 * db] + z1 * s_emb[3 * db + 1] + z2 * s_emb[3 * db + 2];
        ((float2*)o)[h] = make_float2(la, lb);
        if (h == 0) {
            float l8 = z0 * s_emb[24] + z1 * s_emb[25] + z2 * s_emb[26];
            float l9 = z0 * s_emb[27] + z1 * s_emb[28] + z2 * s_emb[29];
            ((float2*)o)[4] = make_float2(l8, l9);
        }
    }
}

extern "C" void kernel_launch(void* const* d_in, const int* in_sizes, int n_in,
                              void* d_out, int out_size) {
    const int*   tok   = (const int*)d_in[0];
    const float* embed = (const float*)d_in[1];
    const float* inw   = (const float*)d_in[2];
    const float* postw = (const float*)d_in[3];
    const float* finw  = (const float*)d_in[4];
    const float* qnw   = (const float*)d_in[5];
    const float* knw   = (const float*)d_in[6];
    const float* kp    = (const float*)d_in[7];
    const float* vp    = (const float*)d_in[8];
    const float* qp    = (const float*)d_in[9];
    const float* op    = (const float*)d_in[10];
    const float* gp    = (const float*)d_in[11];
    const float* upw   = (const float*)d_in[12];
    const float* dp    = (const float*)d_in[13];
    float* out = (float*)d_out;

    k_all<<<128, 512>>>(tok, embed, inw, postw, finw, qnw, knw,
                        kp, vp, qp, op, gp, upw, dp, out);
}

// round 16
// speedup vs baseline: 1.0109x; 1.0109x over previous
#include <cuda_runtime.h>
#include <cuda_bf16.h>
#include <math.h>

#define PCAP 40
#define NEG_INF (-3.4e38f)

__device__ __constant__ float c_cos8[8] = {
    1.0f, 0.5403023058681398f, -0.4161468365471424f, -0.9899924966004454f,
    -0.6536436208636119f, 0.2836621854632263f, 0.9601702866503661f, 0.7539022543433046f
};
__device__ __constant__ float c_sin8[8] = {
    0.0f, 0.8414709848078965f, 0.9092974268256817f, 0.1411200080598672f,
    -0.7568024953079282f, -0.9589242746631385f, -0.27941549819892586f, 0.6569865987187891f
};

// 256 blocks x 512 threads, 2 blocks/SM. block -> (b = blk>>4, chunk = blk&15;
// 64 tokens). Phase 1: warp w -> head w&3, segment (w>>2)*256 + lane*8.
// Phase 2: thread = (token, head, pool-half); octet shfl-reduce.
__global__ void __launch_bounds__(512, 2)
k_all(const int* __restrict__ tok,
      const float* __restrict__ embed,
      const float* __restrict__ inw,
      const float* __restrict__ postw,
      const float* __restrict__ finw,
      const float* __restrict__ qnw,
      const float* __restrict__ knw,
      const float* __restrict__ kp,
      const float* __restrict__ vp,
      const float* __restrict__ qp,
      const float* __restrict__ op,
      const float* __restrict__ gp,
      const float* __restrict__ upw,
      const float* __restrict__ dp,
      float* __restrict__ out) {
    int tid = threadIdx.x;
    int lane = tid & 31, wid = tid >> 5;
    int b = blockIdx.x >> 4;
    int chunk = blockIdx.x & 15;
    int t0 = chunk << 6;
    int tmax = t0 + 63;

    __shared__ int    s_tok[1024];
    __shared__ float  s_emb[30];
    __shared__ float4 s_w[4][10];
    __shared__ float2 s_pool[4][PCAP];
    __shared__ int    s_pn[4];
    __shared__ float  s_sub[4][16];  // inclusive seg-scan max at 64-delta bounds
    __shared__ float  s_M[4][64];    // per-row inclusive prefix max

    // ---------- phase 0: staging (independent loads) ----------
    if (tid < 4) s_pn[tid] = 0;
    if (tid < 256) {
        const int4* rowv = (const int4*)(tok + b * 1024);
        ((int4*)s_tok)[tid] = rowv[tid];
    }
    if (tid < 30) s_emb[tid] = embed[tid];
    if (tid >= 256 && tid < 296) {
        int q = tid - 256;
        int hh = q / 10, dd = q % 10;
        float e0 = embed[3 * dd], e1 = embed[3 * dd + 1], e2 = embed[3 * dd + 2];
        float vv = (e0 * e0 + e1 * e1 + e2 * e2) * (1.0f / 3.0f);
        float rr = rsqrtf(vv + 1e-6f);
        float y0 = e0 * rr * inw[0], y1 = e1 * rr * inw[1], y2 = e2 * rr * inw[2];
        float v0 = vp[0] * y0 + vp[1] * y1 + vp[2] * y2;
        float v1 = vp[3] * y0 + vp[4] * y1 + vp[5] * y2;
        float w0 = v0 * op[0 * 8 + 2 * hh] + v1 * op[0 * 8 + 2 * hh + 1];
        float w1 = v0 * op[1 * 8 + 2 * hh] + v1 * op[1 * 8 + 2 * hh + 1];
        float w2 = v0 * op[2 * 8 + 2 * hh] + v1 * op[2 * 8 + 2 * hh + 1];
        s_w[hh][dd] = make_float4(w0, w1, w2, 0.0f);
    }

    // ---------- phase 1: score scan, 4 warps per head ----------
    int h1 = wid & 3;
    int part = wid >> 2;
    int base = part * 256 + lane * 8;

    float f8[8];
    {
        float e0 = embed[0], e1 = embed[1], e2 = embed[2];
        float vv = (e0 * e0 + e1 * e1 + e2 * e2) * (1.0f / 3.0f);
        float rr = rsqrtf(vv + 1e-6f);
        float xl0 = e0 * rr * inw[0], xl1 = e1 * rr * inw[1], xl2 = e2 * rr * inw[2];
        float k0 = kp[0] * xl0 + kp[1] * xl1 + kp[2] * xl2;
        float k1 = kp[3] * xl0 + kp[4] * xl1 + kp[5] * xl2;
        float rk = rsqrtf((k0 * k0 + k1 * k1) * 0.5f + 1e-6f);
        float kn0 = k0 * rk * knw[0], kn1 = k1 * rk * knw[1];
        const float* q0r = qp + (2 * h1) * 3;
        const float* q1r = qp + (2 * h1 + 1) * 3;
        float q0 = q0r[0] * xl0 + q0r[1] * xl1 + q0r[2] * xl2;
        float q1 = q1r[0] * xl0 + q1r[1] * xl1 + q1r[2] * xl2;
        float rq = rsqrtf((q0 * q0 + q1 * q1) * 0.5f + 1e-6f);
        float qn0 = q0 * rq * qnw[0], qn1 = q1 * rq * qnw[1];
        float P = (qn0 * kn0 + qn1 * kn1) * 0.70710678118654752f;
        float X = (qn0 * kn1 - qn1 * kn0) * 0.70710678118654752f;
        float cb, sb;
        sincosf((float)base, &sb, &cb);
        float A = P * cb + X * sb;
        float B = X * cb - P * sb;
        #pragma unroll
        for (int i = 0; i < 8; i++)
            f8[i] = A * c_cos8[i] + B * c_sin8[i];
    }
    float lm = f8[0];
    #pragma unroll
    for (int i = 1; i < 8; i++) lm = fmaxf(lm, f8[i]);
    float sc = lm;
    #pragma unroll
    for (int off = 1; off < 32; off <<= 1) {
        float v = __shfl_up_sync(0xffffffffu, sc, off);
        if (lane >= off) sc = fmaxf(sc, v);
    }
    // 64-delta boundary maxes (within-segment inclusive scan values)
    if ((lane & 7) == 7) s_sub[h1][part * 4 + (lane >> 3)] = sc;
    __syncthreads();

    {
        // cross-segment exclusive prefix for this warp's segment
        float wpre = NEG_INF;
        #pragma unroll
        for (int p = 0; p < 3; p++)
            if (p < part) wpre = fmaxf(wpre, s_sub[h1][4 * p + 3]);
        float ex = __shfl_up_sync(0xffffffffu, sc, 1);
        float run = fmaxf((lane == 0) ? NEG_INF : ex, wpre);

        // M_low: exclusive global prefix max at t0 = 64*chunk
        int cs = chunk >> 2;        // full 256-segments before t0
        int rq4 = chunk & 3;        // extra 64-blocks
        float M_low = NEG_INF;
        #pragma unroll
        for (int p = 0; p < 3; p++)
            if (p < cs) M_low = fmaxf(M_low, s_sub[h1][4 * p + 3]);
        if (rq4) M_low = fmaxf(M_low, s_sub[h1][4 * cs + rq4 - 1]);
        run = fmaxf(run, M_low);

        if (base <= tmax) {
            #pragma unroll
            for (int i = 0; i < 8; i++) {
                float f = f8[i];
                int delta = base + i;
                if (f >= run - 13.0f && delta <= tmax) {
                    int idx = atomicAdd(&s_pn[h1], 1);
                    if (idx < PCAP)
                        s_pool[h1][idx] = make_float2(__int_as_float(delta), f);
                }
                run = fmaxf(run, f);
                if (delta >= t0 && delta <= tmax)
                    s_M[h1][delta - t0] = run;   // inclusive prefix max
            }
        }
    }
    __syncthreads();

    // ---------- phase 2: thread = (token, head, half); octet reduce ----------
    int t = t0 + (tid >> 3);
    int h = (tid >> 1) & 3;
    int half = tid & 1;
    int pr = tid & 7;
    int d = s_tok[t];
    float x0 = s_emb[3 * d], x1 = s_emb[3 * d + 1], x2 = s_emb[3 * d + 2];

    float cx0, cx1, cx2;
    {
        int n = min(s_pn[h], PCAP);
        float M = s_M[h][t - t0];
        float thr = M - 13.0f;
        float sum = 0.0f, c0 = 0.0f, c1 = 0.0f, c2 = 0.0f;
        for (int j = half; j < n; j += 2) {
            float2 e = s_pool[h][j];
            int dj = __float_as_int(e.x);
            if (dj <= t && e.y > thr) {
                float p = __expf(e.y - M);
                sum += p;
                float4 w = s_w[h][s_tok[t - dj]];
                c0 += p * w.x;
                c1 += p * w.y;
                c2 += p * w.z;
            }
        }
        // merge halves, then normalize
        sum += __shfl_xor_sync(0xffffffffu, sum, 1);
        c0  += __shfl_xor_sync(0xffffffffu, c0, 1);
        c1  += __shfl_xor_sync(0xffffffffu, c1, 1);
        c2  += __shfl_xor_sync(0xffffffffu, c2, 1);
        float inv = 1.0f / sum;
        cx0 = c0 * inv;
        cx1 = c1 * inv;
        cx2 = c2 * inv;
    }
    // merge heads within octet
    #pragma unroll
    for (int off = 2; off < 8; off <<= 1) {
        cx0 += __shfl_xor_sync(0xffffffffu, cx0, off);
        cx1 += __shfl_xor_sync(0xffffffffu, cx1, off);
        cx2 += __shfl_xor_sync(0xffffffffu, cx2, off);
    }
    x0 += cx0;
    x1 += cx1;
    x2 += cx2;

    // ---------- epilogue: post-norm; MLP split 4-ways in octet; logits -------
    float var = (x0 * x0 + x1 * x1 + x2 * x2) * (1.0f / 3.0f);
    float r = rsqrtf(var + 1e-6f);
    float y0 = x0 * r * postw[0];
    float y1 = x1 * r * postw[1];
    float y2 = x2 * r * postw[2];
    float d0, d1, d2;
    {
        int j = h;  // lanes (h,half) duplicate channel h; halved by pairing below
        float g = gp[j * 3] * y0 + gp[j * 3 + 1] * y1 + gp[j * 3 + 2] * y2;
        float u = upw[j * 3] * y0 + upw[j * 3 + 1] * y1 + upw[j * 3 + 2] * y2;
        float sil = g / (1.0f + __expf(-g));
        float hh = sil * u * 0.5f;  // duplicated across half -> halve
        d0 = dp[0 * 4 + j] * hh;
        d1 = dp[1 * 4 + j] * hh;
        d2 = dp[2 * 4 + j] * hh;
    }
    #pragma unroll
    for (int off = 1; off < 8; off <<= 1) {
        d0 += __shfl_xor_sync(0xffffffffu, d0, off);
        d1 += __shfl_xor_sync(0xffffffffu, d1, off);
        d2 += __shfl_xor_sync(0xffffffffu, d2, off);
    }
    x0 += d0;
    x1 += d1;
    x2 += d2;

    float var2 = (x0 * x0 + x1 * x1 + x2 * x2) * (1.0f / 3.0f);
    float r2 = rsqrtf(var2 + 1e-6f);
    float z0 = x0 * r2 * finw[0];
    float z1 = x1 * r2 * finw[1];
    float z2 = x2 * r2 * finw[2];

    if (pr < 5) {
        int da = 2 * pr, db = 2 * pr + 1;
        float la = z0 * s_emb[3 * da] + z1 * s_emb[3 * da + 1] + z2 * s_emb[3 * da + 2];
        float lb = z0 * s_emb[3 * db] + z1 * s_emb[3 * db + 1] + z2 * s_emb[3 * db + 2];
        float2* o2 = (float2*)(out + (size_t)(b * 1024 + t) * 10);
        o2[pr] = make_float2(la, lb);
    }
}

extern "C" void kernel_launch(void* const* d_in, const int* in_sizes, int n_in,
                              void* d_out, int out_size) {
    const int*   tok   = (const int*)d_in[0];
    const float* embed = (const float*)d_in[1];
    const float* inw   = (const float*)d_in[2];
    const float* postw = (const float*)d_in[3];
    const float* finw  = (const float*)d_in[4];
    const float* qnw   = (const float*)d_in[5];
    const float* knw   = (const float*)d_in[6];
    const float* kp    = (const float*)d_in[7];
    const float* vp    = (const float*)d_in[8];
    const float* qp    = (const float*)d_in[9];
    const float* op    = (const float*)d_in[10];
    const float* gp    = (const float*)d_in[11];
    const float* upw   = (const float*)d_in[12];
    const float* dp    = (const float*)d_in[13];
    float* out = (float*)d_out;

    k_all<<<256, 512>>>(tok, embed, inw, postw, finw, qnw, knw,
                        kp, vp, qp, op, gp, upw, dp, out);
}

// round 17
// speedup vs baseline: 1.0817x; 1.0700x over previous
#include <cuda_runtime.h>
#include <cuda_bf16.h>
#include <math.h>

#define WCAP 20
#define NEG_INF (-3.4e38f)

__device__ __constant__ float c_cos8[8] = {
    1.0f, 0.5403023058681398f, -0.4161468365471424f, -0.9899924966004454f,
    -0.6536436208636119f, 0.2836621854632263f, 0.9601702866503661f, 0.7539022543433046f
};
__device__ __constant__ float c_sin8[8] = {
    0.0f, 0.8414709848078965f, 0.9092974268256817f, 0.1411200080598672f,
    -0.7568024953079282f, -0.9589242746631385f, -0.27941549819892586f, 0.6569865987187891f
};

// 128 blocks x 512 threads. block -> (b = blk>>3, chunk = blk&7; 128 tokens).
// Phase 1: warp w -> head w&3, delta segment (w>>2)*256 + lane*8; warp-private
//          pool segment (no atomics); emits per-row prefix max s_M.
// Phase 2: thread = (token, head) quad; segment-bounded pool walk.
__global__ void __launch_bounds__(512)
k_all(const int* __restrict__ tok,
      const float* __restrict__ embed,
      const float* __restrict__ inw,
      const float* __restrict__ postw,
      const float* __restrict__ finw,
      const float* __restrict__ qnw,
      const float* __restrict__ knw,
      const float* __restrict__ kp,
      const float* __restrict__ vp,
      const float* __restrict__ qp,
      const float* __restrict__ op,
      const float* __restrict__ gp,
      const float* __restrict__ upw,
      const float* __restrict__ dp,
      float* __restrict__ out) {
    int tid = threadIdx.x;
    int lane = tid & 31, wid = tid >> 5;
    int b = blockIdx.x >> 3;
    int chunk = blockIdx.x & 7;
    int t0 = chunk << 7;
    int tmax = t0 + 127;

    __shared__ int    s_tok[1024];
    __shared__ float  s_emb[30];
    __shared__ float4 s_w[4][10];
    __shared__ float2 s_pool[4][4 * WCAP];  // per (head, part) segments
    __shared__ int    s_cnt4[4][4];
    __shared__ float  s_part[4][4];  // inclusive max of each 256-delta segment
    __shared__ float  s_half[4][4];  // inclusive max of first 128 of segment
    __shared__ float  s_M[4][128];   // per-row inclusive prefix max

    // ---------- phase 0: staging (independent loads) ----------
    if (tid < 256) {
        const int4* rowv = (const int4*)(tok + b * 1024);
        ((int4*)s_tok)[tid] = rowv[tid];
    }
    if (tid < 30) s_emb[tid] = embed[tid];
    if (tid >= 256 && tid < 296) {
        int q = tid - 256;
        int hh = q / 10, dd = q % 10;
        float e0 = embed[3 * dd], e1 = embed[3 * dd + 1], e2 = embed[3 * dd + 2];
        float vv = (e0 * e0 + e1 * e1 + e2 * e2) * (1.0f / 3.0f);
        float rr = rsqrtf(vv + 1e-6f);
        float y0 = e0 * rr * inw[0], y1 = e1 * rr * inw[1], y2 = e2 * rr * inw[2];
        float v0 = vp[0] * y0 + vp[1] * y1 + vp[2] * y2;
        float v1 = vp[3] * y0 + vp[4] * y1 + vp[5] * y2;
        float w0 = v0 * op[0 * 8 + 2 * hh] + v1 * op[0 * 8 + 2 * hh + 1];
        float w1 = v0 * op[1 * 8 + 2 * hh] + v1 * op[1 * 8 + 2 * hh + 1];
        float w2 = v0 * op[2 * 8 + 2 * hh] + v1 * op[2 * 8 + 2 * hh + 1];
        s_w[hh][dd] = make_float4(w0, w1, w2, 0.0f);
    }

    // ---------- phase 1: score scan, 4 warps per head ----------
    int h1 = wid & 3;
    int part = wid >> 2;
    int base = part * 256 + lane * 8;

    float f8[8];
    if (base <= tmax) {
        float e0 = embed[0], e1 = embed[1], e2 = embed[2];
        float vv = (e0 * e0 + e1 * e1 + e2 * e2) * (1.0f / 3.0f);
        float rr = rsqrtf(vv + 1e-6f);
        float xl0 = e0 * rr * inw[0], xl1 = e1 * rr * inw[1], xl2 = e2 * rr * inw[2];
        float k0 = kp[0] * xl0 + kp[1] * xl1 + kp[2] * xl2;
        float k1 = kp[3] * xl0 + kp[4] * xl1 + kp[5] * xl2;
        float rk = rsqrtf((k0 * k0 + k1 * k1) * 0.5f + 1e-6f);
        float kn0 = k0 * rk * knw[0], kn1 = k1 * rk * knw[1];
        const float* q0r = qp + (2 * h1) * 3;
        const float* q1r = qp + (2 * h1 + 1) * 3;
        float q0 = q0r[0] * xl0 + q0r[1] * xl1 + q0r[2] * xl2;
        float q1 = q1r[0] * xl0 + q1r[1] * xl1 + q1r[2] * xl2;
        float rq = rsqrtf((q0 * q0 + q1 * q1) * 0.5f + 1e-6f);
        float qn0 = q0 * rq * qnw[0], qn1 = q1 * rq * qnw[1];
        float P = (qn0 * kn0 + qn1 * kn1) * 0.70710678118654752f;
        float X = (qn0 * kn1 - qn1 * kn0) * 0.70710678118654752f;
        float cb, sb;
        sincosf((float)base, &sb, &cb);
        float A = P * cb + X * sb;
        float B = X * cb - P * sb;
        #pragma unroll
        for (int i = 0; i < 8; i++)
            f8[i] = A * c_cos8[i] + B * c_sin8[i];
    } else {
        #pragma unroll
        for (int i = 0; i < 8; i++) f8[i] = NEG_INF;
    }
    float lm = f8[0];
    #pragma unroll
    for (int i = 1; i < 8; i++) lm = fmaxf(lm, f8[i]);
    float sc = lm;
    #pragma unroll
    for (int off = 1; off < 32; off <<= 1) {
        float v = __shfl_up_sync(0xffffffffu, sc, off);
        if (lane >= off) sc = fmaxf(sc, v);
    }
    if (lane == 15) s_half[h1][part] = sc;
    if (lane == 31) s_part[h1][part] = sc;
    __syncthreads();

    {
        float wpre = NEG_INF;
        #pragma unroll
        for (int p = 0; p < 3; p++)
            if (p < part) wpre = fmaxf(wpre, s_part[h1][p]);
        float ex = __shfl_up_sync(0xffffffffu, sc, 1);
        float run = fmaxf((lane == 0) ? NEG_INF : ex, wpre);

        // fold exclusive prefix max at t0 into run (exact for delta >= t0)
        int hc = chunk >> 1;
        float M_low = NEG_INF;
        #pragma unroll
        for (int p = 0; p < 3; p++)
            if (p < hc) M_low = fmaxf(M_low, s_part[h1][p]);
        if (chunk & 1) M_low = fmaxf(M_low, s_half[h1][hc]);
        run = fmaxf(run, M_low);

        // warp-private pool push (ballot compaction, no atomics)
        int wcount = 0;
        unsigned lt = (1u << lane) - 1u;
        #pragma unroll
        for (int i = 0; i < 8; i++) {
            float f = f8[i];
            int delta = base + i;
            bool push = (delta <= tmax) && (f >= run - 13.0f);
            unsigned msk = __ballot_sync(0xffffffffu, push);
            if (push) {
                int off = wcount + __popc(msk & lt);
                if (off < WCAP)
                    s_pool[h1][part * WCAP + off] =
                        make_float2(__int_as_float(delta), f);
            }
            wcount += __popc(msk);
            run = fmaxf(run, f);
            if (delta >= t0 && delta <= tmax)
                s_M[h1][delta - t0] = run;   // inclusive prefix max
        }
        if (lane == 0) s_cnt4[h1][part] = min(wcount, WCAP);
    }
    __syncthreads();

    // ---------- phase 2: thread = (token, head); segment-bounded walk -------
    int t = t0 + (tid >> 2);
    int h = tid & 3;
    int d = s_tok[t];
    float x0 = s_emb[3 * d], x1 = s_emb[3 * d + 1], x2 = s_emb[3 * d + 2];

    float cx0, cx1, cx2;
    {
        float M = s_M[h][t - t0];
        float thr = M - 13.0f;
        float sum = 0.0f, c0 = 0.0f, c1 = 0.0f, c2 = 0.0f;
        int segmax = chunk >> 1;   // segments with start <= tmax
        for (int seg = 0; seg <= segmax; seg++) {
            int cnt = s_cnt4[h][seg];
            #pragma unroll 2
            for (int j = 0; j < cnt; j++) {
                float2 e = s_pool[h][seg * WCAP + j];
                int dj = __float_as_int(e.x);
                if (dj <= t && e.y > thr) {
                    float p = __expf(e.y - M);
                    sum += p;
                    float4 w = s_w[h][s_tok[t - dj]];
                    c0 += p * w.x;
                    c1 += p * w.y;
                    c2 += p * w.z;
                }
            }
        }
        float inv = 1.0f / sum;
        cx0 = c0 * inv;
        cx1 = c1 * inv;
        cx2 = c2 * inv;
    }
    #pragma unroll
    for (int off = 1; off < 4; off <<= 1) {
        cx0 += __shfl_xor_sync(0xffffffffu, cx0, off);
        cx1 += __shfl_xor_sync(0xffffffffu, cx1, off);
        cx2 += __shfl_xor_sync(0xffffffffu, cx2, off);
    }
    x0 += cx0;
    x1 += cx1;
    x2 += cx2;

    // ---------- epilogue: post-norm; MLP split across quad; final + logits ---
    float var = (x0 * x0 + x1 * x1 + x2 * x2) * (1.0f / 3.0f);
    float r = rsqrtf(var + 1e-6f);
    float y0 = x0 * r * postw[0];
    float y1 = x1 * r * postw[1];
    float y2 = x2 * r * postw[2];
    float d0, d1, d2;
    {
        int j = h;
        float g = gp[j * 3] * y0 + gp[j * 3 + 1] * y1 + gp[j * 3 + 2] * y2;
        float u = upw[j * 3] * y0 + upw[j * 3 + 1] * y1 + upw[j * 3 + 2] * y2;
        float sil = g / (1.0f + __expf(-g));
        float hh = sil * u;
        d0 = dp[0 * 4 + j] * hh;
        d1 = dp[1 * 4 + j] * hh;
        d2 = dp[2 * 4 + j] * hh;
    }
    #pragma unroll
    for (int off = 1; off < 4; off <<= 1) {
        d0 += __shfl_xor_sync(0xffffffffu, d0, off);
        d1 += __shfl_xor_sync(0xffffffffu, d1, off);
        d2 += __shfl_xor_sync(0xffffffffu, d2, off);
    }
    x0 += d0;
    x1 += d1;
    x2 += d2;

    float var2 = (x0 * x0 + x1 * x1 + x2 * x2) * (1.0f / 3.0f);
    float r2 = rsqrtf(var2 + 1e-6f);
    float z0 = x0 * r2 * finw[0];
    float z1 = x1 * r2 * finw[1];
    float z2 = x2 * r2 * finw[2];

    float* o = out + (size_t)(b * 1024 + t) * 10;
    {
        int da = 2 * h, db = 2 * h + 1;
        float la = z0 * s_emb[3 * da] + z1 * s_emb[3 * da + 1] + z2 * s_emb[3 * da + 2];
        float lb = z0 * s_emb[3 * db] + z1 * s_emb[3 * db + 1] + z2 * s_emb[3 * db + 2];
        ((float2*)o)[h] = make_float2(la, lb);
        if (h == 0) {
            float l8 = z0 * s_emb[24] + z1 * s_emb[25] + z2 * s_emb[26];
            float l9 = z0 * s_emb[27] + z1 * s_emb[28] + z2 * s_emb[29];
            ((float2*)o)[4] = make_float2(l8, l9);
        }
    }
}

extern "C" void kernel_launch(void* const* d_in, const int* in_sizes, int n_in,
                              void* d_out, int out_size) {
    const int*   tok   = (const int*)d_in[0];
    const float* embed = (const float*)d_in[1];
    const float* inw   = (const float*)d_in[2];
    const float* postw = (const float*)d_in[3];
    const float* finw  = (const float*)d_in[4];
    const float* qnw   = (const float*)d_in[5];
    const float* knw   = (const float*)d_in[6];
    const float* kp    = (const float*)d_in[7];
    const float* vp    = (const float*)d_in[8];
    const float* qp    = (const float*)d_in[9];
    const float* op    = (const float*)d_in[10];
    const float* gp    = (const float*)d_in[11];
    const float* upw   = (const float*)d_in[12];
    const float* dp    = (const float*)d_in[13];
    float* out = (float*)d_out;

    k_all<<<128, 512>>>(tok, embed, inw, postw, finw, qnw, knw,
                        kp, vp, qp, op, gp, upw, dp, out);
}